// round 15
// baseline (speedup 1.0000x reference)
#include <cuda_runtime.h>

// PZCell biquad, warp-per-row parallel scan, 3-buffer cp.async ring,
// Cayley-Hamilton k-pair powers (M^n = k1*M - k2*I), scan-level matrices
// hoisted to registers once (reused by all four quarter scans).
// y[t] = b0 x[t] + b1 x[t-1] + b2 x[t-2] - a1 y[t-1] - a2 y[t-2]   (den == 1)

namespace {
constexpr int T_LEN   = 2048;
constexpr int B_ROWS  = 4096;
constexpr int QSTEPS  = 512;                // steps per quarter
constexpr int QTILE   = 512;                // floats per quarter buffer (2KB)
constexpr int NBUF    = 3;                  // ring buffers
constexpr int RPB     = 2;                  // rows (warps) per block
constexpr int THREADS = 32 * RPB;
constexpr int WARP_SMEM  = NBUF * QTILE;    // 1536 floats
constexpr int SMEM_BYTES = RPB * WARP_SMEM * (int)sizeof(float);  // 12288
}

// chunk c (0..31, 16 floats), granule g (0..3): conflict-free for all passes
__device__ __forceinline__ int swz(int c, int g) {
    return c * 16 + ((g ^ ((c >> 1) & 3)) << 2);
}

__device__ __forceinline__ void cp_async16(float* dst, const float* src) {
    unsigned s = (unsigned)__cvta_generic_to_shared(dst);
    asm volatile("cp.async.cg.shared.global [%0], [%1], 16;" :: "r"(s), "l"(src));
}
__device__ __forceinline__ void cp_commit() { asm volatile("cp.async.commit_group;"); }
template <int N>
__device__ __forceinline__ void cp_wait() {
    asm volatile("cp.async.wait_group %0;" :: "n"(N) : "memory");
}

struct Coef { float a1, a2, A2, Bc, b0, b1, b2; };
struct K2   { float k1, k2; };   // k1*M - k2*I
struct ScanK { K2 l0, l1, l2, l3, l4; };   // M^16, M^32, M^64, M^128, M^256

__device__ __forceinline__ K2 ksq(K2 a, float a1, float a2) {
    float t = a.k1 * a.k1;
    K2 r;
    r.k1 = -fmaf(a1, t, 2.f * a.k1 * a.k2);
    r.k2 =  fmaf(a2, t, -a.k2 * a.k2);
    return r;
}
__device__ __forceinline__ K2 kmul(K2 p, K2 q, float a1, float a2) {
    float t = p.k1 * q.k1;
    K2 r;
    r.k1 = -fmaf(a1, t, fmaf(p.k1, q.k2, p.k2 * q.k1));
    r.k2 =  fmaf(a2, t, -p.k2 * q.k2);
    return r;
}

// one scan level: combine from lane-dist d using k-pair m
__device__ __forceinline__ void scan_level(float& vx, float& vy, K2 m,
                                           float a1, float a2, int lane, int d)
{
    float ox = __shfl_up_sync(0xffffffffu, vx, d);
    float oy = __shfl_up_sync(0xffffffffu, vy, d);
    if (lane >= d) {
        float t = fmaf(-a1, ox, -a2 * oy);
        vx = fmaf(m.k1, t,  fmaf(-m.k2, ox, vx));
        vy = fmaf(m.k1, ox, fmaf(-m.k2, oy, vy));
    }
}

// issue one quarter's coalesced cp.async load into buf
__device__ __forceinline__ void issue_quarter_load(
    float* buf, const float* __restrict__ xq, int lane)
{
    #pragma unroll
    for (int k = 0; k < 4; ++k) {
        int ch = k * 8 + (lane >> 2);
        cp_async16(buf + swz(ch, lane & 3), xq + k * 128 + lane * 4);
    }
    cp_commit();
}

// one 512-step quarter. Px,Py = row exit state (updated); bx1,bx2 = x tail.
__device__ __forceinline__ void quarter_pass(
    float* buf, float* __restrict__ yq, int lane, const Coef& c,
    float W1, float W2, const ScanK& S,
    float& Px, float& Py, float& bx1, float& bx2)
{
    const float a1 = c.a1, a2 = c.a2;

    // ---- boundary x[-1], x[-2] ----
    float x1, x2;
    if (lane > 0) {
        int cc = lane - 1;
        int off = cc * 16 + ((3 ^ ((cc >> 1) & 3)) << 2);   // granule 3 = f 12..15
        x1 = buf[off + 3];   // f=15
        x2 = buf[off + 2];   // f=14
    } else {
        x1 = bx1; x2 = bx2;
    }
    __syncwarp();

    // ---- Phase A: zero-entry-state recurrence in place ----
    float p = 0.f, q = 0.f;
    #pragma unroll
    for (int g = 0; g < 4; ++g) {
        float4 xv = *reinterpret_cast<float4*>(buf + swz(lane, g));
        float u0 = fmaf(c.b0, xv.x, fmaf(c.b1, x1,   c.b2 * x2));
        float u1 = fmaf(c.b0, xv.y, fmaf(c.b1, xv.x, c.b2 * x1));
        float u2 = fmaf(c.b0, xv.z, fmaf(c.b1, xv.y, c.b2 * xv.x));
        float u3 = fmaf(c.b0, xv.w, fmaf(c.b1, xv.z, c.b2 * xv.y));
        x2 = xv.z; x1 = xv.w;
        float w1 = fmaf(-a1, u0, u1);
        float w3 = fmaf(-a1, u2, u3);
        float yA = fmaf(-a1, p,  fmaf(-a2, q,  u0));
        float yB = fmaf( c.A2, p,  fmaf( c.Bc, q,  w1));
        float yC = fmaf(-a1, yB, fmaf(-a2, yA, u2));
        float yD = fmaf( c.A2, yB, fmaf( c.Bc, yA, w3));
        p = yD; q = yC;
        *reinterpret_cast<float4*>(buf + swz(lane, g)) = make_float4(yA, yB, yC, yD);
    }
    // x tail of this quarter (lane 31 holds x[511], x[510])
    float nbx1 = __shfl_sync(0xffffffffu, x1, 31);
    float nbx2 = __shfl_sync(0xffffffffu, x2, 31);
    bx1 = nbx1; bx2 = nbx2;

    // ---- seeded affine Kogge-Stone scan (levels hoisted in S) ----
    float vx = p, vy = q;
    if (lane == 0) {   // fold row carry into seed: d0' = d0 + M^16 * P
        float t = fmaf(-a1, Px, -a2 * Py);
        vx = fmaf(S.l0.k1, t,  fmaf(-S.l0.k2, Px, vx));
        vy = fmaf(S.l0.k1, Px, fmaf(-S.l0.k2, Py, vy));
    }
    scan_level(vx, vy, S.l0, a1, a2, lane, 1);
    scan_level(vx, vy, S.l1, a1, a2, lane, 2);
    scan_level(vx, vy, S.l2, a1, a2, lane, 4);
    scan_level(vx, vy, S.l3, a1, a2, lane, 8);
    scan_level(vx, vy, S.l4, a1, a2, lane, 16);

    // exclusive entry per 16-step chunk; lane 0 entry = carried P
    float ex = __shfl_up_sync(0xffffffffu, vx, 1);
    float ey = __shfl_up_sync(0xffffffffu, vy, 1);
    if (lane == 0) { ex = Px; ey = Py; }
    // row exit state = inclusive at lane 31 (carry included via seed)
    Px = __shfl_sync(0xffffffffu, vx, 31);
    Py = __shfl_sync(0xffffffffu, vy, 31);

    __syncwarp();

    // ---- store pass with fused homogeneous correction ----
    // t = k*128 + lane*4: chunk ch = 8k + (lane>>2), f0 = (lane&3)*4,
    // seed = W * entry with W = M^f0 as k-pair (W1,W2).
    #pragma unroll
    for (int k = 0; k < 4; ++k) {
        int ch = k * 8 + (lane >> 2);
        float exc = __shfl_sync(0xffffffffu, ex, ch);
        float eyc = __shfl_sync(0xffffffffu, ey, ch);
        float t  = fmaf(-a1, exc, -a2 * eyc);
        float s1 = fmaf(W1, t,   -W2 * exc);
        float s2 = fmaf(W1, exc, -W2 * eyc);
        float hA = fmaf(-a1, s1, -a2 * s2);
        float hB = fmaf( c.A2, s1,  c.Bc * s2);
        float hC = fmaf(-a1, hB, -a2 * hA);
        float hD = fmaf( c.A2, hB,  c.Bc * hA);
        float4 zv = *reinterpret_cast<float4*>(buf + swz(ch, lane & 3));
        zv.x += hA; zv.y += hB; zv.z += hC; zv.w += hD;
        *reinterpret_cast<float4*>(yq + k * 128 + lane * 4) = zv;
    }
    __syncwarp();
}

__global__ void __launch_bounds__(THREADS, 14)
pzF_kernel(const float* __restrict__ x, const float* __restrict__ gain_ri,
           const float* __restrict__ poles_ri, const float* __restrict__ zeros_ri,
           float* __restrict__ out)
{
    extern __shared__ float sbuf[];
    const int lane = threadIdx.x & 31;
    const int w    = threadIdx.x >> 5;
    const int row  = blockIdx.x * RPB + w;
    const float* xr = x   + (long)row * T_LEN;
    float*       yr = out + (long)row * T_LEN;
    float* sb = sbuf + w * WARP_SMEM;

    // ---- issue loads for quarters 0..2 (3 commit groups) ----
    issue_quarter_load(sb + 0 * QTILE, xr + 0 * QSTEPS, lane);
    issue_quarter_load(sb + 1 * QTILE, xr + 1 * QSTEPS, lane);
    issue_quarter_load(sb + 2 * QTILE, xr + 2 * QSTEPS, lane);

    // ---- coefficients + hoisted k-pair powers (overlap with cp.async) ----
    Coef c;
    {
        const float gr = gain_ri[0],  gi = gain_ri[1];
        const float pr0 = poles_ri[0], pi0 = poles_ri[1];
        const float pr1 = poles_ri[2], pi1 = poles_ri[3];
        const float zr0 = zeros_ri[0], zi0 = zeros_ri[1];
        const float zr1 = zeros_ri[2], zi1 = zeros_ri[3];
        c.a1 = -(pr0 + pr1);
        c.a2 = pr0 * pr1 - pi0 * pi1;
        const float zc1r = -(zr0 + zr1), zc1i = -(zi0 + zi1);
        const float zc2r = zr0 * zr1 - zi0 * zi1;
        const float zc2i = zr0 * zi1 + zi0 * zr1;
        c.b0 = gr;
        c.b1 = gr * zc1r - gi * zc1i;
        c.b2 = gr * zc2r - gi * zc2i;
        c.A2 = c.a1 * c.a1 - c.a2;
        c.Bc = c.a1 * c.a2;
    }
    const float a1 = c.a1, a2 = c.a2;
    K2 M1k  = { 1.f, 0.f };
    K2 M4k  = ksq(ksq(M1k, a1, a2), a1, a2);
    K2 M8k  = ksq(M4k, a1, a2);
    K2 M12k = kmul(M8k, M4k, a1, a2);
    ScanK S;
    S.l0 = ksq(M8k,  a1, a2);   // M^16
    S.l1 = ksq(S.l0, a1, a2);   // M^32
    S.l2 = ksq(S.l1, a1, a2);   // M^64
    S.l3 = ksq(S.l2, a1, a2);   // M^128
    S.l4 = ksq(S.l3, a1, a2);   // M^256
    // W = M^(4*(lane&3)) as k-pair
    const int j = lane & 3;
    const float W1 = (j == 0) ? 0.f  : (j == 1) ? M4k.k1 : (j == 2) ? M8k.k1 : M12k.k1;
    const float W2 = (j == 0) ? -1.f : (j == 1) ? M4k.k2 : (j == 2) ? M8k.k2 : M12k.k2;

    float Px = 0.f, Py = 0.f;     // row exit state carry
    float bx1 = 0.f, bx2 = 0.f;   // x tail carry

    cp_wait<2>(); __syncwarp();   // q0 resident
    quarter_pass(sb + 0 * QTILE, yr + 0 * QSTEPS, lane, c, W1, W2, S, Px, Py, bx1, bx2);

    // buf0 drained -> issue q3 into it (hidden under q1+q2 compute)
    issue_quarter_load(sb + 0 * QTILE, xr + 3 * QSTEPS, lane);

    cp_wait<2>(); __syncwarp();   // q1 resident (q2, q3 may be outstanding)
    quarter_pass(sb + 1 * QTILE, yr + 1 * QSTEPS, lane, c, W1, W2, S, Px, Py, bx1, bx2);
    cp_wait<1>(); __syncwarp();   // q2 resident
    quarter_pass(sb + 2 * QTILE, yr + 2 * QSTEPS, lane, c, W1, W2, S, Px, Py, bx1, bx2);
    cp_wait<0>(); __syncwarp();   // q3 resident
    quarter_pass(sb + 0 * QTILE, yr + 3 * QSTEPS, lane, c, W1, W2, S, Px, Py, bx1, bx2);
}

extern "C" void kernel_launch(void* const* d_in, const int* in_sizes, int n_in,
                              void* d_out, int out_size) {
    (void)in_sizes; (void)n_in; (void)out_size;
    const float* x        = (const float*)d_in[0];
    const float* gain_ri  = (const float*)d_in[1];
    const float* poles_ri = (const float*)d_in[2];
    const float* zeros_ri = (const float*)d_in[3];
    float* out = (float*)d_out;

    cudaFuncSetAttribute(pzF_kernel, cudaFuncAttributeMaxDynamicSharedMemorySize, SMEM_BYTES);
    pzF_kernel<<<B_ROWS / RPB, THREADS, SMEM_BYTES>>>(x, gain_ri, poles_ri, zeros_ri, out);
}

// round 16
// speedup vs baseline: 1.0201x; 1.0201x over previous
#include <cuda_runtime.h>

// PZCell biquad, warp-per-row parallel scan, PAIRED quarters (ILP-2 on
// Phase A and on the Kogge-Stone scans; one shared ksq chain per pair).
// y[t] = b0 x[t] + b1 x[t-1] + b2 x[t-2] - a1 y[t-1] - a2 y[t-2]   (den == 1)
// Matrix powers as Cayley-Hamilton k-pairs: M^n = k1*M - k2*I.

namespace {
constexpr int T_LEN   = 2048;
constexpr int B_ROWS  = 4096;
constexpr int QSTEPS  = 512;                // steps per quarter
constexpr int QTILE   = 512;                // floats per quarter buffer (2KB)
constexpr int RPB     = 2;                  // rows (warps) per block
constexpr int THREADS = 32 * RPB;
constexpr int WARP_SMEM  = 4 * QTILE;       // 4 resident quarter buffers
constexpr int SMEM_BYTES = RPB * WARP_SMEM * (int)sizeof(float);  // 16384
}

// chunk c (0..31, 16 floats), granule g (0..3): conflict-free for all passes
__device__ __forceinline__ int swz(int c, int g) {
    return c * 16 + ((g ^ ((c >> 1) & 3)) << 2);
}

__device__ __forceinline__ void cp_async16(float* dst, const float* src) {
    unsigned s = (unsigned)__cvta_generic_to_shared(dst);
    asm volatile("cp.async.cg.shared.global [%0], [%1], 16;" :: "r"(s), "l"(src));
}
__device__ __forceinline__ void cp_commit() { asm volatile("cp.async.commit_group;"); }
template <int N>
__device__ __forceinline__ void cp_wait() {
    asm volatile("cp.async.wait_group %0;" :: "n"(N) : "memory");
}

struct Coef { float a1, a2, A2, Bc, b0, b1, b2; };
struct K2   { float k1, k2; };   // k1*M - k2*I

__device__ __forceinline__ K2 ksq(K2 a, float a1, float a2) {
    float t = a.k1 * a.k1;
    K2 r;
    r.k1 = -fmaf(a1, t, 2.f * a.k1 * a.k2);
    r.k2 =  fmaf(a2, t, -a.k2 * a.k2);
    return r;
}
__device__ __forceinline__ K2 kmul(K2 p, K2 q, float a1, float a2) {
    float t = p.k1 * q.k1;
    K2 r;
    r.k1 = -fmaf(a1, t, fmaf(p.k1, q.k2, p.k2 * q.k1));
    r.k2 =  fmaf(a2, t, -p.k2 * q.k2);
    return r;
}

// 4 recurrence steps; updates (x1,x2,p,q), returns z quad
__device__ __forceinline__ float4 step4(const Coef& c, float4 xv,
                                        float& x1, float& x2, float& p, float& q)
{
    float u0 = fmaf(c.b0, xv.x, fmaf(c.b1, x1,   c.b2 * x2));
    float u1 = fmaf(c.b0, xv.y, fmaf(c.b1, xv.x, c.b2 * x1));
    float u2 = fmaf(c.b0, xv.z, fmaf(c.b1, xv.y, c.b2 * xv.x));
    float u3 = fmaf(c.b0, xv.w, fmaf(c.b1, xv.z, c.b2 * xv.y));
    x2 = xv.z; x1 = xv.w;
    float w1 = fmaf(-c.a1, u0, u1);
    float w3 = fmaf(-c.a1, u2, u3);
    float yA = fmaf(-c.a1, p,  fmaf(-c.a2, q,  u0));
    float yB = fmaf( c.A2, p,  fmaf( c.Bc, q,  w1));
    float yC = fmaf(-c.a1, yB, fmaf(-c.a2, yA, u2));
    float yD = fmaf( c.A2, yB, fmaf( c.Bc, yA, w3));
    p = yD; q = yC;
    return make_float4(yA, yB, yC, yD);
}

__device__ __forceinline__ void issue_quarter_load(
    float* buf, const float* __restrict__ xq, int lane)
{
    #pragma unroll
    for (int k = 0; k < 4; ++k) {
        int ch = k * 8 + (lane >> 2);
        cp_async16(buf + swz(ch, lane & 3), xq + k * 128 + lane * 4);
    }
    cp_commit();
}

// fused-correction coalesced store for one quarter (R12-proven)
__device__ __forceinline__ void store_quarter(
    float* buf, float* __restrict__ yq, int lane, const Coef& c,
    float W1, float W2, float ex, float ey)
{
    const float a1 = c.a1, a2 = c.a2;
    #pragma unroll
    for (int k = 0; k < 4; ++k) {
        int ch = k * 8 + (lane >> 2);
        float exc = __shfl_sync(0xffffffffu, ex, ch);
        float eyc = __shfl_sync(0xffffffffu, ey, ch);
        float t  = fmaf(-a1, exc, -a2 * eyc);
        float s1 = fmaf(W1, t,   -W2 * exc);
        float s2 = fmaf(W1, exc, -W2 * eyc);
        float hA = fmaf(-a1, s1, -a2 * s2);
        float hB = fmaf( c.A2, s1,  c.Bc * s2);
        float hC = fmaf(-a1, hB, -a2 * hA);
        float hD = fmaf( c.A2, hB,  c.Bc * hA);
        float4 zv = *reinterpret_cast<float4*>(buf + swz(ch, lane & 3));
        zv.x += hA; zv.y += hB; zv.z += hC; zv.w += hD;
        *reinterpret_cast<float4*>(yq + k * 128 + lane * 4) = zv;
    }
}

// one pair of quarters (qa = even, qb = odd), interleaved chains.
template <bool BUILD>
__device__ __forceinline__ void pair_pass(
    float* bA, float* bB, float* __restrict__ yA, float* __restrict__ yB,
    int lane, const Coef& c, float W1, float W2, K2 M16k,
    K2& A, K2& M512k, float& Px, float& Py, float& bx1, float& bx2)
{
    const float a1 = c.a1, a2 = c.a2;

    // ---- boundaries (all reads before any Phase A writes) ----
    float x1a, x2a, x1b, x2b;
    if (lane > 0) {
        int cc = lane - 1;
        int off = cc * 16 + ((3 ^ ((cc >> 1) & 3)) << 2);
        x1a = bA[off + 3];  x2a = bA[off + 2];
        x1b = bB[off + 3];  x2b = bB[off + 2];
    } else {
        x1a = bx1; x2a = bx2;
        x1b = bA[496 + 3];  x2b = bA[496 + 2];   // qa tail (chunk 31, swz g3 -> 496)
        bx1 = bB[496 + 3];  bx2 = bB[496 + 2];   // carry x tail for next pair
    }
    __syncwarp();

    // ---- Phase A: both quarters, interleaved independent chains ----
    float pa = 0.f, qa = 0.f, pb = 0.f, qb = 0.f;
    #pragma unroll
    for (int g = 0; g < 4; ++g) {
        float4 xva = *reinterpret_cast<float4*>(bA + swz(lane, g));
        float4 xvb = *reinterpret_cast<float4*>(bB + swz(lane, g));
        float4 za = step4(c, xva, x1a, x2a, pa, qa);
        float4 zb = step4(c, xvb, x1b, x2b, pb, qb);
        *reinterpret_cast<float4*>(bA + swz(lane, g)) = za;
        *reinterpret_cast<float4*>(bB + swz(lane, g)) = zb;
    }

    // ---- two interleaved Kogge-Stone scans, shared ksq chain ----
    K2 m = M16k;
    float vax = pa, vay = qa, vbx = pb, vby = qb;
    if (lane == 0) {   // seed qa with row carry: d0' = d0 + M16*P
        float t = fmaf(-a1, Px, -a2 * Py);
        vax = fmaf(m.k1, t,  fmaf(-m.k2, Px, vax));
        vay = fmaf(m.k1, Px, fmaf(-m.k2, Py, vay));
    }
    if (BUILD) A = K2{ 0.f, -1.f };   // identity
    #pragma unroll
    for (int i = 0; i < 5; ++i) {
        int d = 1 << i;
        float oax = __shfl_up_sync(0xffffffffu, vax, d);
        float oay = __shfl_up_sync(0xffffffffu, vay, d);
        float obx = __shfl_up_sync(0xffffffffu, vbx, d);
        float oby = __shfl_up_sync(0xffffffffu, vby, d);
        if (lane >= d) {
            float ta = fmaf(-a1, oax, -a2 * oay);
            vax = fmaf(m.k1, ta,  fmaf(-m.k2, oax, vax));
            vay = fmaf(m.k1, oax, fmaf(-m.k2, oay, vay));
            float tb = fmaf(-a1, obx, -a2 * oby);
            vbx = fmaf(m.k1, tb,  fmaf(-m.k2, obx, vbx));
            vby = fmaf(m.k1, obx, fmaf(-m.k2, oby, vby));
        }
        if (BUILD && ((lane >> i) & 1)) A = kmul(m, A, a1, a2);
        if (i < 4) m = ksq(m, a1, a2);
    }
    if (BUILD) M512k = ksq(m, a1, a2);   // m = M^256 after loop

    // ---- entries and carries ----
    float eax = __shfl_up_sync(0xffffffffu, vax, 1);
    float eay = __shfl_up_sync(0xffffffffu, vay, 1);
    if (lane == 0) { eax = Px; eay = Py; }             // qa entries (true)
    float ebx = __shfl_up_sync(0xffffffffu, vbx, 1);
    float eby = __shfl_up_sync(0xffffffffu, vby, 1);
    if (lane == 0) { ebx = 0.f; eby = 0.f; }           // qb zero-entry entries
    // C = true exit of qa (seed carried it)
    float Cx = __shfl_sync(0xffffffffu, vax, 31);
    float Cy = __shfl_sync(0xffffffffu, vay, 31);
    // qb true entries: E = A_lane * C + e0
    {
        float t = fmaf(-a1, Cx, -a2 * Cy);
        ebx = fmaf(A.k1, t,  fmaf(-A.k2, Cx, ebx));
        eby = fmaf(A.k1, Cx, fmaf(-A.k2, Cy, eby));
    }
    // pair exit: P' = M512 * C + D_b
    float Dbx = __shfl_sync(0xffffffffu, vbx, 31);
    float Dby = __shfl_sync(0xffffffffu, vby, 31);
    {
        float t = fmaf(-a1, Cx, -a2 * Cy);
        Px = fmaf(M512k.k1, t,  fmaf(-M512k.k2, Cx, Dbx));
        Py = fmaf(M512k.k1, Cx, fmaf(-M512k.k2, Cy, Dby));
    }
    __syncwarp();   // Phase A z writes visible before transposed reads

    // ---- fused-correction coalesced stores ----
    store_quarter(bA, yA, lane, c, W1, W2, eax, eay);
    store_quarter(bB, yB, lane, c, W1, W2, ebx, eby);
    __syncwarp();
}

__global__ void __launch_bounds__(THREADS, 14)
pzG_kernel(const float* __restrict__ x, const float* __restrict__ gain_ri,
           const float* __restrict__ poles_ri, const float* __restrict__ zeros_ri,
           float* __restrict__ out)
{
    extern __shared__ float sbuf[];
    const int lane = threadIdx.x & 31;
    const int w    = threadIdx.x >> 5;
    const int row  = blockIdx.x * RPB + w;
    const float* xr = x   + (long)row * T_LEN;
    float*       yr = out + (long)row * T_LEN;
    float* sb = sbuf + w * WARP_SMEM;

    // ---- issue all 4 quarter loads up front (4 commit groups) ----
    issue_quarter_load(sb + 0 * QTILE, xr + 0 * QSTEPS, lane);
    issue_quarter_load(sb + 1 * QTILE, xr + 1 * QSTEPS, lane);
    issue_quarter_load(sb + 2 * QTILE, xr + 2 * QSTEPS, lane);
    issue_quarter_load(sb + 3 * QTILE, xr + 3 * QSTEPS, lane);

    // ---- coefficients + k-pair powers (overlap with cp.async) ----
    Coef c;
    {
        const float gr = gain_ri[0],  gi = gain_ri[1];
        const float pr0 = poles_ri[0], pi0 = poles_ri[1];
        const float pr1 = poles_ri[2], pi1 = poles_ri[3];
        const float zr0 = zeros_ri[0], zi0 = zeros_ri[1];
        const float zr1 = zeros_ri[2], zi1 = zeros_ri[3];
        c.a1 = -(pr0 + pr1);
        c.a2 = pr0 * pr1 - pi0 * pi1;
        const float zc1r = -(zr0 + zr1), zc1i = -(zi0 + zi1);
        const float zc2r = zr0 * zr1 - zi0 * zi1;
        const float zc2i = zr0 * zi1 + zi0 * zr1;
        c.b0 = gr;
        c.b1 = gr * zc1r - gi * zc1i;
        c.b2 = gr * zc2r - gi * zc2i;
        c.A2 = c.a1 * c.a1 - c.a2;
        c.Bc = c.a1 * c.a2;
    }
    const float a1 = c.a1, a2 = c.a2;
    K2 M1k  = { 1.f, 0.f };
    K2 M4k  = ksq(ksq(M1k, a1, a2), a1, a2);
    K2 M8k  = ksq(M4k, a1, a2);
    K2 M16k = ksq(M8k, a1, a2);
    K2 M12k = kmul(M8k, M4k, a1, a2);
    // W = M^(4*(lane&3)) as k-pair
    const int j = lane & 3;
    const float W1 = (j == 0) ? 0.f  : (j == 1) ? M4k.k1 : (j == 2) ? M8k.k1 : M12k.k1;
    const float W2 = (j == 0) ? -1.f : (j == 1) ? M4k.k2 : (j == 2) ? M8k.k2 : M12k.k2;

    K2 A, M512k;                   // built in first pair, reused in second
    float Px = 0.f, Py = 0.f;      // row exit state carry
    float bx1 = 0.f, bx2 = 0.f;    // x tail carry (lane 0)

    cp_wait<2>(); __syncwarp();    // q0, q1 resident (q2, q3 streaming)
    pair_pass<true>(sb + 0 * QTILE, sb + 1 * QTILE,
                    yr + 0 * QSTEPS, yr + 1 * QSTEPS,
                    lane, c, W1, W2, M16k, A, M512k, Px, Py, bx1, bx2);

    cp_wait<0>(); __syncwarp();    // q2, q3 resident
    pair_pass<false>(sb + 2 * QTILE, sb + 3 * QTILE,
                     yr + 2 * QSTEPS, yr + 3 * QSTEPS,
                     lane, c, W1, W2, M16k, A, M512k, Px, Py, bx1, bx2);
}

extern "C" void kernel_launch(void* const* d_in, const int* in_sizes, int n_in,
                              void* d_out, int out_size) {
    (void)in_sizes; (void)n_in; (void)out_size;
    const float* x        = (const float*)d_in[0];
    const float* gain_ri  = (const float*)d_in[1];
    const float* poles_ri = (const float*)d_in[2];
    const float* zeros_ri = (const float*)d_in[3];
    float* out = (float*)d_out;

    cudaFuncSetAttribute(pzG_kernel, cudaFuncAttributeMaxDynamicSharedMemorySize, SMEM_BYTES);
    pzG_kernel<<<B_ROWS / RPB, THREADS, SMEM_BYTES>>>(x, gain_ri, poles_ri, zeros_ri, out);
}